// round 14
// baseline (speedup 1.0000x reference)
#include <cuda_runtime.h>
#include <math.h>
#include <stdint.h>

// Fixed problem shapes
#define BB   4
#define SS   2048
#define GG   8
#define DD   128
#define NN   64
#define BG   (BB*GG)          // 32
#define NTOK (BB*SS*GG)       // 65536
#define SUB  16
#define NSUB (SS/SUB)         // 128

// Scratch (device globals; no allocation allowed)
__device__ float4 g_hc[BG*SS*NN];      // (hl_r, hl_i, c_r, c_i)  64 MB
__device__ float2 g_hin[BG*NSUB*NN];   // sub16 input states       2 MB

// ---------------- helpers ----------------
__device__ __forceinline__ uint32_t cvt_tf32(float f) {
    uint32_t u; asm("cvt.rna.tf32.f32 %0, %1;" : "=r"(u) : "f"(f)); return u;
}
__device__ __forceinline__ float tf32f(float f) {
    return __uint_as_float(cvt_tf32(f));
}
__device__ __forceinline__ void mma8(float* c, uint32_t a0, uint32_t a1,
                                     uint32_t a2, uint32_t a3,
                                     uint32_t b0, uint32_t b1) {
    asm("mma.sync.aligned.m16n8k8.row.col.f32.tf32.tf32.f32 "
        "{%0,%1,%2,%3}, {%4,%5,%6,%7}, {%8,%9}, {%0,%1,%2,%3};"
        : "+f"(c[0]), "+f"(c[1]), "+f"(c[2]), "+f"(c[3])
        : "r"(a0), "r"(a1), "r"(a2), "r"(a3), "r"(b0), "r"(b1));
}
__device__ __forceinline__ float clampdt(float v) {
    return fminf(fmaxf(v, 1e-4f), 2.0f);
}
__device__ __forceinline__ void gbar(int id) {
    asm volatile("bar.sync %0, %1;" :: "r"(id), "r"(128) : "memory");
}
// packed column position: pairs (k, k+4) adjacent for LDS.64 fragment loads
__device__ __forceinline__ int unpos(int c) {
    int slot = c & 7;
    return (c & ~7) + (slot >> 1) + ((slot & 1) << 2);
}
__device__ __forceinline__ int posf(int k) {
    return (k & ~7) + ((k & 3) << 1) + ((k & 4) >> 2);
}

// ---------------------------------------------------------------------------
// Kernel 1: tf32 MMA projection + in-warp 16-token affine scan.
// block 512 = 4 independent groups of 4 warps. Group owns one 16-token slice;
// warp p owns n-tiles {2p, 2p+1} for BOTH cr and ci (20 accumulator floats;
// warp 0 also carries the dt tile). dt exchanged via smem + named barrier.
// Persistent grid 296, 2 CTAs/SM -> 32 warps.
// ---------------------------------------------------------------------------
__global__ __launch_bounds__(512, 2) void k1_mma(
    const float* __restrict__ xr_g, const float* __restrict__ xi_g,
    const float* __restrict__ logA, const float* __restrict__ Aph_g,
    const float* __restrict__ Bwr,  const float* __restrict__ Bwi,
    const float* __restrict__ dtw_g, const float* __restrict__ dtb_g)
{
    extern __shared__ float sm[];
    float*  BRp = sm;                    // [72][136]
    float*  BIp = BRp + 72*136;          // [72][136]
    float*  nlA = BIp + 72*136;          // [512]
    float*  aph = nlA + 512;             // [512]
    float2* dts = (float2*)(aph + 512);  // [4 groups][16 tokens]

    const int tid = threadIdx.x;
    for (int idx = tid; idx < 72*136; idx += 512) {
        int r = idx / 136, c = idx - r*136;
        float vr = 0.f, vi = 0.f;
        if (c < 128 && r < 66) {
            int k = unpos(c);
            if (r < 64)      { vr = Bwr[r*128 + k];   vi = Bwi[r*128 + k]; }
            else if (r == 64){ vr = dtw_g[k];         vi = dtw_g[128 + k]; }
            else             { vr = dtw_g[256 + k];   vi = dtw_g[384 + k]; }
        }
        BRp[idx] = tf32f(vr);
        BIp[idx] = tf32f(vi);
    }
    if (tid < 512) {
        nlA[tid] = -log1pf(expf(logA[tid]));   // -softplus
        aph[tid] = Aph_g[tid];
    }
    __syncthreads();

    const int w = tid >> 5, l = tid & 31;
    const int q = l >> 2, j = l & 3;
    const int gw = w >> 2, p = w & 3;
    const float db0 = dtb_g[0], db1 = dtb_g[1];
    float2* mydts = dts + gw*16;
    const int barid = 1 + gw;

    for (int slice = blockIdx.x*4 + gw; slice < 4096; slice += gridDim.x*4) {
        const int bg = slice >> 7, s16 = slice & 127;
        const int b = bg >> 3, g = bg & 7;
        const int g6 = g*64;

        float cr2[2][4], ci2[2][4], dta[4];
        #pragma unroll
        for (int t = 0; t < 2; ++t) {
            cr2[t][0]=0.f; cr2[t][1]=0.f; cr2[t][2]=0.f; cr2[t][3]=0.f;
            ci2[t][0]=0.f; ci2[t][1]=0.f; ci2[t][2]=0.f; ci2[t][3]=0.f;
        }
        dta[0]=0.f; dta[1]=0.f; dta[2]=0.f; dta[3]=0.f;

        const size_t rowA = (size_t)((b*2048 + s16*16 + q)*8 + g)*128;
        const size_t rowB = rowA + (size_t)8*1024;
        const int rA = (2*p)*8 + q;     // B-row base of tile ntA
        const int rB = (2*p + 1)*8 + q; // tile ntB
        const int rD = 64 + q;          // dt tile rows

        // ---- xr half: cr += xr*Bwr ; ci += xr*Bwi ; dt += xr*dtw_lo ----
        #pragma unroll 4
        for (int ks = 0; ks < 16; ++ks) {
            const int kk = ks*8 + j;
            uint32_t a0 = cvt_tf32(xr_g[rowA + kk]);
            uint32_t a1 = cvt_tf32(xr_g[rowB + kk]);
            uint32_t a2 = cvt_tf32(xr_g[rowA + kk + 4]);
            uint32_t a3 = cvt_tf32(xr_g[rowB + kk + 4]);
            const int kc = ks*8 + 2*j;
            uint2 bb;
            bb = *(const uint2*)&BRp[rA*136 + kc];
            mma8(cr2[0], a0, a1, a2, a3, bb.x, bb.y);
            bb = *(const uint2*)&BRp[rB*136 + kc];
            mma8(cr2[1], a0, a1, a2, a3, bb.x, bb.y);
            if (p == 0) {
                bb = *(const uint2*)&BRp[rD*136 + kc];
                mma8(dta, a0, a1, a2, a3, bb.x, bb.y);
            }
            bb = *(const uint2*)&BIp[rA*136 + kc];
            mma8(ci2[0], a0, a1, a2, a3, bb.x, bb.y);
            bb = *(const uint2*)&BIp[rB*136 + kc];
            mma8(ci2[1], a0, a1, a2, a3, bb.x, bb.y);
        }
        // ---- xi half: cr -= xi*Bwi ; ci += xi*Bwr ; dt += xi*dtw_hi ----
        #pragma unroll 4
        for (int ks = 0; ks < 16; ++ks) {
            const int kk = ks*8 + j;
            uint32_t a0 = cvt_tf32(xi_g[rowA + kk]);
            uint32_t a1 = cvt_tf32(xi_g[rowB + kk]);
            uint32_t a2 = cvt_tf32(xi_g[rowA + kk + 4]);
            uint32_t a3 = cvt_tf32(xi_g[rowB + kk + 4]);
            const int kc = ks*8 + 2*j;
            uint2 bb;
            bb = *(const uint2*)&BIp[rA*136 + kc];
            mma8(cr2[0], a0, a1, a2, a3, bb.x ^ 0x80000000u, bb.y ^ 0x80000000u);
            bb = *(const uint2*)&BIp[rB*136 + kc];
            mma8(cr2[1], a0, a1, a2, a3, bb.x ^ 0x80000000u, bb.y ^ 0x80000000u);
            if (p == 0) {
                bb = *(const uint2*)&BIp[rD*136 + kc];   // +dtw (no negate)
                mma8(dta, a0, a1, a2, a3, bb.x, bb.y);
            }
            bb = *(const uint2*)&BRp[rA*136 + kc];
            mma8(ci2[0], a0, a1, a2, a3, bb.x, bb.y);
            bb = *(const uint2*)&BRp[rB*136 + kc];
            mma8(ci2[1], a0, a1, a2, a3, bb.x, bb.y);
        }

        // ---- dt publish (warp 0 of group) ----
        if (p == 0) {
            const int src = l & ~3;
            float dmL = __shfl_sync(0xffffffffu, dta[0], src);
            float dpL = __shfl_sync(0xffffffffu, dta[1], src);
            float dmH = __shfl_sync(0xffffffffu, dta[2], src);
            float dpH = __shfl_sync(0xffffffffu, dta[3], src);
            dmL = clampdt(__expf(dmL + db0));  dpL = clampdt(__expf(dpL + db1));
            dmH = clampdt(__expf(dmH + db0));  dpH = clampdt(__expf(dpH + db1));
            if (j == 0) {
                mydts[q]     = make_float2(dmL, dpL);
                mydts[q + 8] = make_float2(dmH, dpH);
            }
        }
        gbar(barid);
        const float2 dL = mydts[q];
        const float2 dH = mydts[q + 8];

        // ---- per-n: affine elements (MUFU), 16-token shfl scan, write ----
        const size_t idxL = ((size_t)bg*2048 + s16*16 + q)*64;
        const size_t idxH = idxL + (size_t)8*64;

        #pragma unroll
        for (int tt = 0; tt < 2; ++tt) {
            const int nt = 2*p + tt;
            #pragma unroll
            for (int e = 0; e < 2; ++e) {
                const int n = nt*8 + 2*j + e;
                const float nl = nlA[g6 + n], ap = aph[g6 + n];
                float snL, csL, snH, csH;
                float amL = __expf(dL.x*nl);
                __sincosf(dL.y*ap, &snL, &csL);
                float aLr = amL*csL, aLi = amL*snL;
                float bLr = cr2[tt][e]*dL.x, bLi = ci2[tt][e]*dL.x;
                float amH = __expf(dH.x*nl);
                __sincosf(dH.y*ap, &snH, &csH);
                float aHr = amH*csH, aHi = amH*snH;
                float bHr = cr2[tt][2+e]*dH.x, bHi = ci2[tt][2+e]*dH.x;

                // Hillis-Steele over q (both token-halves simultaneously)
                #pragma unroll
                for (int st = 1; st <= 4; st <<= 1) {
                    const int dlt = 4*st;
                    float par = __shfl_up_sync(0xffffffffu, aLr, dlt);
                    float pai = __shfl_up_sync(0xffffffffu, aLi, dlt);
                    float pbr = __shfl_up_sync(0xffffffffu, bLr, dlt);
                    float pbi = __shfl_up_sync(0xffffffffu, bLi, dlt);
                    float qar = __shfl_up_sync(0xffffffffu, aHr, dlt);
                    float qai = __shfl_up_sync(0xffffffffu, aHi, dlt);
                    float qbr = __shfl_up_sync(0xffffffffu, bHr, dlt);
                    float qbi = __shfl_up_sync(0xffffffffu, bHi, dlt);
                    if (q >= st) {
                        float t1 = aLr*par - aLi*pai;
                        float t2 = aLr*pai + aLi*par;
                        float t3 = fmaf(aLr, pbr, fmaf(-aLi, pbi, bLr));
                        float t4 = fmaf(aLr, pbi, fmaf( aLi, pbr, bLi));
                        aLr = t1; aLi = t2; bLr = t3; bLi = t4;
                        t1 = aHr*qar - aHi*qai;
                        t2 = aHr*qai + aHi*qar;
                        t3 = fmaf(aHr, qbr, fmaf(-aHi, qbi, bHr));
                        t4 = fmaf(aHr, qbi, fmaf( aHi, qbr, bHi));
                        aHr = t1; aHi = t2; bHr = t3; bHi = t4;
                    }
                }
                // bridge: full prefix of tokens 0..7 lives at q==7 (lane 28+j)
                float f7ar = __shfl_sync(0xffffffffu, aLr, 28 + j);
                float f7ai = __shfl_sync(0xffffffffu, aLi, 28 + j);
                float f7br = __shfl_sync(0xffffffffu, bLr, 28 + j);
                float f7bi = __shfl_sync(0xffffffffu, bLi, 28 + j);
                float Har = aHr*f7ar - aHi*f7ai;
                float Hai = aHr*f7ai + aHi*f7ar;
                float Hbr = fmaf(aHr, f7br, fmaf(-aHi, f7bi, bHr));
                float Hbi = fmaf(aHr, f7bi, fmaf( aHi, f7br, bHi));

                g_hc[idxL + n] = make_float4(bLr, bLi, aLr, aLi);   // token q
                g_hc[idxH + n] = make_float4(Hbr, Hbi, Har, Hai);   // token q+8
            }
        }
        gbar(barid);   // protect mydts before next iteration's publish
    }
}

// ---------------------------------------------------------------------------
// Kernel 2b: sequential sub16 combine; renorm every 16th sub16 boundary.
// ---------------------------------------------------------------------------
__global__ __launch_bounds__(64) void k2b_combine(void)
{
    int bg = blockIdx.x;
    int n = threadIdx.x;
    float hr = 0.f, hi = 0.f;

    float4 ebuf[8];
    #pragma unroll
    for (int jj = 0; jj < 8; ++jj)
        ebuf[jj] = g_hc[((size_t)bg*SS + jj*SUB + 15)*NN + n];

    for (int s0 = 0; s0 < NSUB; s0 += 8) {
        #pragma unroll
        for (int jj = 0; jj < 8; ++jj) {
            float4 e = ebuf[jj];
            int nsub = s0 + 8 + jj;
            if (nsub < NSUB)
                ebuf[jj] = g_hc[((size_t)bg*SS + nsub*SUB + 15)*NN + n];
            int sub = s0 + jj;
            g_hin[(bg*NSUB + sub)*NN + n] = make_float2(hr, hi);
            float nr = fmaf(e.z, hr, fmaf(-e.w, hi, e.x));
            float ni = fmaf(e.z, hi, fmaf( e.w, hr, e.y));
            if ((sub & 15) == 15) {
                float nm = sqrtf(nr*nr + ni*ni + 1e-8f);
                float sc = fminf(nm, 100.0f)/nm;
                nr *= sc; ni *= sc;
            }
            hr = nr; hi = ni;
        }
    }
}

// ---------------------------------------------------------------------------
// Kernel 3: correction + tf32 MMA C-projection. Persistent (grid 296),
// CTA tile = 64 tokens, block 512, 2 CTAs/SM; P/Q fill amortized.
// ---------------------------------------------------------------------------
__global__ __launch_bounds__(512, 2) void k3_mma(
    const float* __restrict__ Cwr, const float* __restrict__ Cwi,
    float* __restrict__ out)
{
    extern __shared__ float sm[];
    float* P  = sm;             // [128 d][72]  Cwr, k-pair packed
    float* Q  = P + 128*72;     // [128 d][72]  Cwi
    float* hs = Q + 128*72;     // [64 tok][136]  [hr | hi], k-pair packed

    const int tid = threadIdx.x;
    for (int idx = tid; idx < 128*72; idx += 512) {
        int d = idx / 72, c = idx - d*72;
        float vp = 0.f, vq = 0.f;
        if (c < 64) {
            int k = unpos(c);
            vp = Cwr[d*64 + k];
            vq = Cwi[d*64 + k];
        }
        P[idx] = tf32f(vp);
        Q[idx] = tf32f(vq);
    }

    const int w = tid >> 5, l = tid & 31;
    const int q = l >> 2, j = l & 3;
    const int mrow  = w & 3;           // which 16-token block
    const int nhalf = (w >> 2) & 1;    // which 8 nt-tiles
    const int half  = w >> 3;          // 0 = yR, 1 = yI
    const int row0 = mrow*16 + q;
    const int ntb = nhalf*8;

    const float* Blo = half ? Q : P;     // k < 64
    const float* Bhi = half ? P : Q;     // k >= 64
    const uint32_t mhi = half ? 0u : 0x80000000u;   // negate Q for yR
    float* outh = out + (size_t)half * ((size_t)NTOK*128);

    for (int tile = blockIdx.x; tile < NTOK/64; tile += gridDim.x) {
        const int tau_base = tile*64;

        // ---- correction prologue: 64 tok x 64 n ----
        #pragma unroll
        for (int ii = 0; ii < 8; ++ii) {
            int cell = ii*512 + tid;
            int tl = cell >> 6, n = cell & 63;
            int tau = tau_base + tl;
            int b = tau >> 14, g = tau & 7, s = (tau >> 3) & 2047;
            int bg = b*8 + g;
            float4 hc = g_hc[((size_t)bg*2048 + s)*64 + n];
            float2 hin = g_hin[(bg*NSUB + (s >> 4))*64 + n];
            float hr = fmaf(hc.z, hin.x, fmaf(-hc.w, hin.y, hc.x));
            float hi = fmaf(hc.z, hin.y, fmaf( hc.w, hin.x, hc.y));
            if ((s & 255) == 255) {
                float nm = sqrtf(hr*hr + hi*hi + 1e-8f);
                float sc = fminf(nm, 100.0f)/nm;
                hr *= sc; hi *= sc;
            }
            int pos = posf(n);
            hs[tl*136 + pos]      = tf32f(hr);
            hs[tl*136 + 64 + pos] = tf32f(hi);
        }
        __syncthreads();

        float y[8][4];
        #pragma unroll
        for (int t = 0; t < 8; ++t) { y[t][0]=0.f; y[t][1]=0.f; y[t][2]=0.f; y[t][3]=0.f; }

        // ---- hr half (k < 64) ----
        #pragma unroll
        for (int ks = 0; ks < 8; ++ks) {
            const int kc = ks*8 + 2*j;
            uint2 aa0 = *(const uint2*)&hs[row0*136 + kc];
            uint2 aa1 = *(const uint2*)&hs[(row0 + 8)*136 + kc];
            #pragma unroll
            for (int t = 0; t < 8; ++t) {
                uint2 bb = *(const uint2*)&Blo[((ntb + t)*8 + q)*72 + kc];
                mma8(y[t], aa0.x, aa1.x, aa0.y, aa1.y, bb.x, bb.y);
            }
        }
        // ---- hi half (k >= 64) ----
        #pragma unroll
        for (int ks = 0; ks < 8; ++ks) {
            const int kc = ks*8 + 2*j;
            uint2 aa0 = *(const uint2*)&hs[row0*136 + 64 + kc];
            uint2 aa1 = *(const uint2*)&hs[(row0 + 8)*136 + 64 + kc];
            #pragma unroll
            for (int t = 0; t < 8; ++t) {
                uint2 bb = *(const uint2*)&Bhi[((ntb + t)*8 + q)*72 + kc];
                mma8(y[t], aa0.x, aa1.x, aa0.y, aa1.y, bb.x ^ mhi, bb.y ^ mhi);
            }
        }

        // ---- output ----
        #pragma unroll
        for (int t = 0; t < 8; ++t) {
            int d0 = (ntb + t)*8 + 2*j;
            size_t tA = (size_t)(tau_base + row0)*128 + d0;
            size_t tB = (size_t)(tau_base + row0 + 8)*128 + d0;
            *(float2*)&outh[tA] = make_float2(y[t][0], y[t][1]);
            *(float2*)&outh[tB] = make_float2(y[t][2], y[t][3]);
        }
        __syncthreads();   // protect hs before next tile's prologue
    }
}

// ---------------------------------------------------------------------------
extern "C" void kernel_launch(void* const* d_in, const int* in_sizes, int n_in,
                              void* d_out, int out_size)
{
    const float* x_r  = (const float*)d_in[0];
    const float* x_i  = (const float*)d_in[1];
    const float* logA = (const float*)d_in[2];
    const float* Aph  = (const float*)d_in[3];
    const float* Bwr  = (const float*)d_in[4];
    const float* Bwi  = (const float*)d_in[5];
    const float* Cwr  = (const float*)d_in[6];
    const float* Cwi  = (const float*)d_in[7];
    const float* dtw  = (const float*)d_in[8];
    const float* dtb  = (const float*)d_in[9];
    float* out = (float*)d_out;

    const int smem1 = (72*136*2 + 512*2 + 128) * 4;   // 82,944 B
    const int smem3 = (128*72*2 + 64*136) * 4;        // 108,544 B
    cudaFuncSetAttribute(k1_mma, cudaFuncAttributeMaxDynamicSharedMemorySize, smem1);
    cudaFuncSetAttribute(k3_mma, cudaFuncAttributeMaxDynamicSharedMemorySize, smem3);

    k1_mma<<<296, 512, smem1>>>(x_r, x_i, logA, Aph, Bwr, Bwi, dtw, dtb);
    k2b_combine<<<BG, 64>>>();
    k3_mma<<<296, 512, smem3>>>(Cwr, Cwi, out);
}

// round 15
// speedup vs baseline: 1.1830x; 1.1830x over previous
#include <cuda_runtime.h>
#include <math.h>
#include <stdint.h>

// Fixed problem shapes
#define BB   4
#define SS   2048
#define GG   8
#define DD   128
#define NN   64
#define BG   (BB*GG)          // 32
#define NTOK (BB*SS*GG)       // 65536
#define SUB  16
#define NSUB (SS/SUB)         // 128

// Scratch (device globals; no allocation allowed)
__device__ float4 g_hc[BG*SS*NN];      // (hl_r, hl_i, c_r, c_i)  64 MB
__device__ float2 g_hin[BG*NSUB*NN];   // sub16 input states       2 MB

// ---------------- helpers ----------------
__device__ __forceinline__ uint32_t cvt_tf32(float f) {
    uint32_t u; asm("cvt.rna.tf32.f32 %0, %1;" : "=r"(u) : "f"(f)); return u;
}
__device__ __forceinline__ float tf32f(float f) {
    return __uint_as_float(cvt_tf32(f));
}
__device__ __forceinline__ void mma8(float* c, uint32_t a0, uint32_t a1,
                                     uint32_t a2, uint32_t a3,
                                     uint32_t b0, uint32_t b1) {
    asm("mma.sync.aligned.m16n8k8.row.col.f32.tf32.tf32.f32 "
        "{%0,%1,%2,%3}, {%4,%5,%6,%7}, {%8,%9}, {%0,%1,%2,%3};"
        : "+f"(c[0]), "+f"(c[1]), "+f"(c[2]), "+f"(c[3])
        : "r"(a0), "r"(a1), "r"(a2), "r"(a3), "r"(b0), "r"(b1));
}
__device__ __forceinline__ float clampdt(float v) {
    return fminf(fmaxf(v, 1e-4f), 2.0f);
}
// packed column position: pairs (k, k+4) adjacent for LDS.64 fragment loads
__device__ __forceinline__ int unpos(int c) {
    int slot = c & 7;
    return (c & ~7) + (slot >> 1) + ((slot & 1) << 2);
}
__device__ __forceinline__ int posf(int k) {
    return (k & ~7) + ((k & 3) << 1) + ((k & 4) >> 2);
}

// ---------------------------------------------------------------------------
// Kernel 1: tf32 MMA projection + in-warp 16-token affine scan. Persistent
// (grid 256 -> every warp exactly 2 slices). A-fragments prefetched one ks
// ahead (explicit registers); 32-bit row offsets free the needed headroom.
// ---------------------------------------------------------------------------
__global__ __launch_bounds__(256, 2) void k1_mma(
    const float* __restrict__ xr_g, const float* __restrict__ xi_g,
    const float* __restrict__ logA, const float* __restrict__ Aph_g,
    const float* __restrict__ Bwr,  const float* __restrict__ Bwi,
    const float* __restrict__ dtw_g, const float* __restrict__ dtb_g)
{
    extern __shared__ float sm[];
    float* BRp = sm;                 // [72][136]
    float* BIp = BRp + 72*136;       // [72][136]
    float* nlA = BIp + 72*136;       // [512]
    float* aph = nlA + 512;          // [512]

    const int tid = threadIdx.x;
    for (int idx = tid; idx < 72*136; idx += 256) {
        int r = idx / 136, c = idx - r*136;
        float vr = 0.f, vi = 0.f;
        if (c < 128 && r < 66) {
            int k = unpos(c);
            if (r < 64)      { vr = Bwr[r*128 + k];   vi = Bwi[r*128 + k]; }
            else if (r == 64){ vr = dtw_g[k];         vi = dtw_g[128 + k]; }
            else             { vr = dtw_g[256 + k];   vi = dtw_g[384 + k]; }
        }
        BRp[idx] = tf32f(vr);
        BIp[idx] = tf32f(vi);
    }
    for (int i = tid; i < 512; i += 256) {
        nlA[i] = -log1pf(expf(logA[i]));   // -softplus
        aph[i] = Aph_g[i];
    }
    __syncthreads();

    const int w = tid >> 5, l = tid & 31;
    const int q = l >> 2, j = l & 3;
    const float db0 = dtb_g[0], db1 = dtb_g[1];

    for (int grp = blockIdx.x; grp < 512; grp += gridDim.x) {
        const int slice = grp*8 + w;          // 0..4095
        const int bg = slice >> 7, s16 = slice & 127;
        const int b = bg >> 3, g = bg & 7;
        const int g6 = g*64;

        float cr[9][4], ci[8][4];
        #pragma unroll
        for (int t = 0; t < 9; ++t) { cr[t][0]=0.f; cr[t][1]=0.f; cr[t][2]=0.f; cr[t][3]=0.f; }
        #pragma unroll
        for (int t = 0; t < 8; ++t) { ci[t][0]=0.f; ci[t][1]=0.f; ci[t][2]=0.f; ci[t][3]=0.f; }

        const unsigned rowA = (unsigned)((b*2048 + s16*16 + q)*8 + g)*128u;
        const unsigned rowB = rowA + 8u*1024u;

        // preload ks=0 (xr)
        uint32_t na0 = cvt_tf32(xr_g[rowA + j]);
        uint32_t na1 = cvt_tf32(xr_g[rowB + j]);
        uint32_t na2 = cvt_tf32(xr_g[rowA + j + 4]);
        uint32_t na3 = cvt_tf32(xr_g[rowB + j + 4]);

        // ---- xr half ----
        #pragma unroll 2
        for (int ks = 0; ks < 16; ++ks) {
            const uint32_t a0 = na0, a1 = na1, a2 = na2, a3 = na3;
            // prefetch next fragments (last iter preloads xi ks=0)
            {
                const float* nx = (ks < 15) ? xr_g : xi_g;
                const unsigned kkn = (ks < 15) ? (unsigned)((ks + 1)*8 + j)
                                               : (unsigned)j;
                na0 = cvt_tf32(nx[rowA + kkn]);
                na1 = cvt_tf32(nx[rowB + kkn]);
                na2 = cvt_tf32(nx[rowA + kkn + 4]);
                na3 = cvt_tf32(nx[rowB + kkn + 4]);
            }
            const int kc = ks*8 + 2*j;
            #pragma unroll
            for (int nt = 0; nt < 9; ++nt) {
                uint2 bb = *(const uint2*)&BRp[(nt*8 + q)*136 + kc];
                mma8(cr[nt], a0, a1, a2, a3, bb.x, bb.y);
            }
            #pragma unroll
            for (int nt = 0; nt < 8; ++nt) {
                uint2 bb = *(const uint2*)&BIp[(nt*8 + q)*136 + kc];
                mma8(ci[nt], a0, a1, a2, a3, bb.x, bb.y);
            }
        }
        // ---- xi half ----
        #pragma unroll 2
        for (int ks = 0; ks < 16; ++ks) {
            const uint32_t a0 = na0, a1 = na1, a2 = na2, a3 = na3;
            {
                const unsigned kkn = (ks < 15) ? (unsigned)((ks + 1)*8 + j)
                                               : (unsigned)j;   // harmless reload
                na0 = cvt_tf32(xi_g[rowA + kkn]);
                na1 = cvt_tf32(xi_g[rowB + kkn]);
                na2 = cvt_tf32(xi_g[rowA + kkn + 4]);
                na3 = cvt_tf32(xi_g[rowB + kkn + 4]);
            }
            const int kc = ks*8 + 2*j;
            #pragma unroll
            for (int nt = 0; nt < 9; ++nt) {
                uint2 bb = *(const uint2*)&BIp[(nt*8 + q)*136 + kc];
                uint32_t m = (nt < 8) ? 0x80000000u : 0u;   // -Bwi, but +dtw
                mma8(cr[nt], a0, a1, a2, a3, bb.x ^ m, bb.y ^ m);
            }
            #pragma unroll
            for (int nt = 0; nt < 8; ++nt) {
                uint2 bb = *(const uint2*)&BRp[(nt*8 + q)*136 + kc];
                mma8(ci[nt], a0, a1, a2, a3, bb.x, bb.y);
            }
        }

        // ---- dt via shfl, clamp ----
        const int src = l & ~3;
        float dmL = __shfl_sync(0xffffffffu, cr[8][0], src);
        float dpL = __shfl_sync(0xffffffffu, cr[8][1], src);
        float dmH = __shfl_sync(0xffffffffu, cr[8][2], src);
        float dpH = __shfl_sync(0xffffffffu, cr[8][3], src);
        dmL = clampdt(__expf(dmL + db0));  dpL = clampdt(__expf(dpL + db1));
        dmH = clampdt(__expf(dmH + db0));  dpH = clampdt(__expf(dpH + db1));

        // ---- per-n: affine elements (MUFU), 16-token shfl scan, write ----
        const size_t idxL = ((size_t)bg*2048 + s16*16 + q)*64;
        const size_t idxH = idxL + (size_t)8*64;

        #pragma unroll
        for (int nt = 0; nt < 8; ++nt) {
            #pragma unroll
            for (int e = 0; e < 2; ++e) {
                const int n = nt*8 + 2*j + e;
                const float nl = nlA[g6 + n], ap = aph[g6 + n];
                float snL, csL, snH, csH;
                float amL = __expf(dmL*nl);
                __sincosf(dpL*ap, &snL, &csL);
                float aLr = amL*csL, aLi = amL*snL;
                float bLr = cr[nt][e]*dmL, bLi = ci[nt][e]*dmL;
                float amH = __expf(dmH*nl);
                __sincosf(dpH*ap, &snH, &csH);
                float aHr = amH*csH, aHi = amH*snH;
                float bHr = cr[nt][2+e]*dmH, bHi = ci[nt][2+e]*dmH;

                // Hillis-Steele over q (both halves simultaneously)
                #pragma unroll
                for (int st = 1; st <= 4; st <<= 1) {
                    const int dlt = 4*st;
                    float par = __shfl_up_sync(0xffffffffu, aLr, dlt);
                    float pai = __shfl_up_sync(0xffffffffu, aLi, dlt);
                    float pbr = __shfl_up_sync(0xffffffffu, bLr, dlt);
                    float pbi = __shfl_up_sync(0xffffffffu, bLi, dlt);
                    float qar = __shfl_up_sync(0xffffffffu, aHr, dlt);
                    float qai = __shfl_up_sync(0xffffffffu, aHi, dlt);
                    float qbr = __shfl_up_sync(0xffffffffu, bHr, dlt);
                    float qbi = __shfl_up_sync(0xffffffffu, bHi, dlt);
                    if (q >= st) {
                        float t1 = aLr*par - aLi*pai;
                        float t2 = aLr*pai + aLi*par;
                        float t3 = fmaf(aLr, pbr, fmaf(-aLi, pbi, bLr));
                        float t4 = fmaf(aLr, pbi, fmaf( aLi, pbr, bLi));
                        aLr = t1; aLi = t2; bLr = t3; bLi = t4;
                        t1 = aHr*qar - aHi*qai;
                        t2 = aHr*qai + aHi*qar;
                        t3 = fmaf(aHr, qbr, fmaf(-aHi, qbi, bHr));
                        t4 = fmaf(aHr, qbi, fmaf( aHi, qbr, bHi));
                        aHr = t1; aHi = t2; bHr = t3; bHi = t4;
                    }
                }
                // bridge: full prefix of tokens 0..7 lives at q==7 (lane 28+j)
                float f7ar = __shfl_sync(0xffffffffu, aLr, 28 + j);
                float f7ai = __shfl_sync(0xffffffffu, aLi, 28 + j);
                float f7br = __shfl_sync(0xffffffffu, bLr, 28 + j);
                float f7bi = __shfl_sync(0xffffffffu, bLi, 28 + j);
                float Har = aHr*f7ar - aHi*f7ai;
                float Hai = aHr*f7ai + aHi*f7ar;
                float Hbr = fmaf(aHr, f7br, fmaf(-aHi, f7bi, bHr));
                float Hbi = fmaf(aHr, f7bi, fmaf( aHi, f7br, bHi));

                g_hc[idxL + n] = make_float4(bLr, bLi, aLr, aLi);   // token q
                g_hc[idxH + n] = make_float4(Hbr, Hbi, Har, Hai);   // token q+8
            }
        }
    }
}

// ---------------------------------------------------------------------------
// Kernel 2b: sequential sub16 combine; renorm every 16th sub16 boundary.
// ---------------------------------------------------------------------------
__global__ __launch_bounds__(64) void k2b_combine(void)
{
    int bg = blockIdx.x;
    int n = threadIdx.x;
    float hr = 0.f, hi = 0.f;

    float4 ebuf[8];
    #pragma unroll
    for (int jj = 0; jj < 8; ++jj)
        ebuf[jj] = g_hc[((size_t)bg*SS + jj*SUB + 15)*NN + n];

    for (int s0 = 0; s0 < NSUB; s0 += 8) {
        #pragma unroll
        for (int jj = 0; jj < 8; ++jj) {
            float4 e = ebuf[jj];
            int nsub = s0 + 8 + jj;
            if (nsub < NSUB)
                ebuf[jj] = g_hc[((size_t)bg*SS + nsub*SUB + 15)*NN + n];
            int sub = s0 + jj;
            g_hin[(bg*NSUB + sub)*NN + n] = make_float2(hr, hi);
            float nr = fmaf(e.z, hr, fmaf(-e.w, hi, e.x));
            float ni = fmaf(e.z, hi, fmaf( e.w, hr, e.y));
            if ((sub & 15) == 15) {
                float nm = sqrtf(nr*nr + ni*ni + 1e-8f);
                float sc = fminf(nm, 100.0f)/nm;
                nr *= sc; ni *= sc;
            }
            hr = nr; hi = ni;
        }
    }
}

// ---------------------------------------------------------------------------
// Kernel 3: correction + tf32 MMA C-projection. Persistent (grid 256 ->
// every CTA exactly 4 tiles), CTA tile = 64 tokens, block 512, 2 CTAs/SM.
// ---------------------------------------------------------------------------
__global__ __launch_bounds__(512, 2) void k3_mma(
    const float* __restrict__ Cwr, const float* __restrict__ Cwi,
    float* __restrict__ out)
{
    extern __shared__ float sm[];
    float* P  = sm;             // [128 d][72]  Cwr, k-pair packed
    float* Q  = P + 128*72;     // [128 d][72]  Cwi
    float* hs = Q + 128*72;     // [64 tok][136]  [hr | hi], k-pair packed

    const int tid = threadIdx.x;
    for (int idx = tid; idx < 128*72; idx += 512) {
        int d = idx / 72, c = idx - d*72;
        float vp = 0.f, vq = 0.f;
        if (c < 64) {
            int k = unpos(c);
            vp = Cwr[d*64 + k];
            vq = Cwi[d*64 + k];
        }
        P[idx] = tf32f(vp);
        Q[idx] = tf32f(vq);
    }

    const int w = tid >> 5, l = tid & 31;
    const int q = l >> 2, j = l & 3;
    const int mrow  = w & 3;           // which 16-token block
    const int nhalf = (w >> 2) & 1;    // which 8 nt-tiles
    const int half  = w >> 3;          // 0 = yR, 1 = yI
    const int row0 = mrow*16 + q;
    const int ntb = nhalf*8;

    const float* Blo = half ? Q : P;     // k < 64
    const float* Bhi = half ? P : Q;     // k >= 64
    const uint32_t mhi = half ? 0u : 0x80000000u;   // negate Q for yR
    float* outh = out + (size_t)half * ((size_t)NTOK*128);

    for (int tile = blockIdx.x; tile < NTOK/64; tile += gridDim.x) {
        const int tau_base = tile*64;

        // ---- correction prologue: 64 tok x 64 n ----
        #pragma unroll
        for (int ii = 0; ii < 8; ++ii) {
            int cell = ii*512 + tid;
            int tl = cell >> 6, n = cell & 63;
            int tau = tau_base + tl;
            int b = tau >> 14, g = tau & 7, s = (tau >> 3) & 2047;
            int bg = b*8 + g;
            float4 hc = g_hc[((size_t)bg*2048 + s)*64 + n];
            float2 hin = g_hin[(bg*NSUB + (s >> 4))*64 + n];
            float hr = fmaf(hc.z, hin.x, fmaf(-hc.w, hin.y, hc.x));
            float hi = fmaf(hc.z, hin.y, fmaf( hc.w, hin.x, hc.y));
            if ((s & 255) == 255) {
                float nm = sqrtf(hr*hr + hi*hi + 1e-8f);
                float sc = fminf(nm, 100.0f)/nm;
                hr *= sc; hi *= sc;
            }
            int pos = posf(n);
            hs[tl*136 + pos]      = tf32f(hr);
            hs[tl*136 + 64 + pos] = tf32f(hi);
        }
        __syncthreads();

        float y[8][4];
        #pragma unroll
        for (int t = 0; t < 8; ++t) { y[t][0]=0.f; y[t][1]=0.f; y[t][2]=0.f; y[t][3]=0.f; }

        // ---- hr half (k < 64) ----
        #pragma unroll
        for (int ks = 0; ks < 8; ++ks) {
            const int kc = ks*8 + 2*j;
            uint2 aa0 = *(const uint2*)&hs[row0*136 + kc];
            uint2 aa1 = *(const uint2*)&hs[(row0 + 8)*136 + kc];
            #pragma unroll
            for (int t = 0; t < 8; ++t) {
                uint2 bb = *(const uint2*)&Blo[((ntb + t)*8 + q)*72 + kc];
                mma8(y[t], aa0.x, aa1.x, aa0.y, aa1.y, bb.x, bb.y);
            }
        }
        // ---- hi half (k >= 64) ----
        #pragma unroll
        for (int ks = 0; ks < 8; ++ks) {
            const int kc = ks*8 + 2*j;
            uint2 aa0 = *(const uint2*)&hs[row0*136 + 64 + kc];
            uint2 aa1 = *(const uint2*)&hs[(row0 + 8)*136 + 64 + kc];
            #pragma unroll
            for (int t = 0; t < 8; ++t) {
                uint2 bb = *(const uint2*)&Bhi[((ntb + t)*8 + q)*72 + kc];
                mma8(y[t], aa0.x, aa1.x, aa0.y, aa1.y, bb.x ^ mhi, bb.y ^ mhi);
            }
        }

        // ---- output ----
        #pragma unroll
        for (int t = 0; t < 8; ++t) {
            int d0 = (ntb + t)*8 + 2*j;
            size_t tA = (size_t)(tau_base + row0)*128 + d0;
            size_t tB = (size_t)(tau_base + row0 + 8)*128 + d0;
            *(float2*)&outh[tA] = make_float2(y[t][0], y[t][1]);
            *(float2*)&outh[tB] = make_float2(y[t][2], y[t][3]);
        }
        __syncthreads();   // protect hs before next tile's prologue
    }
}

// ---------------------------------------------------------------------------
extern "C" void kernel_launch(void* const* d_in, const int* in_sizes, int n_in,
                              void* d_out, int out_size)
{
    const float* x_r  = (const float*)d_in[0];
    const float* x_i  = (const float*)d_in[1];
    const float* logA = (const float*)d_in[2];
    const float* Aph  = (const float*)d_in[3];
    const float* Bwr  = (const float*)d_in[4];
    const float* Bwi  = (const float*)d_in[5];
    const float* Cwr  = (const float*)d_in[6];
    const float* Cwi  = (const float*)d_in[7];
    const float* dtw  = (const float*)d_in[8];
    const float* dtb  = (const float*)d_in[9];
    float* out = (float*)d_out;

    const int smem1 = (72*136*2 + 1024) * 4;          // 82,432 B
    const int smem3 = (128*72*2 + 64*136) * 4;        // 108,544 B
    cudaFuncSetAttribute(k1_mma, cudaFuncAttributeMaxDynamicSharedMemorySize, smem1);
    cudaFuncSetAttribute(k3_mma, cudaFuncAttributeMaxDynamicSharedMemorySize, smem3);

    k1_mma<<<256, 256, smem1>>>(x_r, x_i, logA, Aph, Bwr, Bwi, dtw, dtb);
    k2b_combine<<<BG, 64>>>();
    k3_mma<<<256, 512, smem3>>>(Cwr, Cwi, out);
}

// round 16
// speedup vs baseline: 1.3320x; 1.1260x over previous
#include <cuda_runtime.h>
#include <math.h>
#include <stdint.h>

// Fixed problem shapes
#define BB   4
#define SS   2048
#define GG   8
#define DD   128
#define NN   64
#define BG   (BB*GG)          // 32
#define NTOK (BB*SS*GG)       // 65536
#define SUB  16
#define NSUB (SS/SUB)         // 128

// Scratch (device globals; no allocation allowed)
__device__ float4 g_hc[BG*SS*NN];      // (hl_r, hl_i, c_r, c_i)  64 MB
__device__ float2 g_hin[BG*NSUB*NN];   // sub16 input states       2 MB

// ---------------- helpers ----------------
__device__ __forceinline__ uint32_t cvt_tf32(float f) {
    uint32_t u; asm("cvt.rna.tf32.f32 %0, %1;" : "=r"(u) : "f"(f)); return u;
}
__device__ __forceinline__ float tf32f(float f) {
    return __uint_as_float(cvt_tf32(f));
}
__device__ __forceinline__ void mma8(float* c, uint32_t a0, uint32_t a1,
                                     uint32_t a2, uint32_t a3,
                                     uint32_t b0, uint32_t b1) {
    asm("mma.sync.aligned.m16n8k8.row.col.f32.tf32.tf32.f32 "
        "{%0,%1,%2,%3}, {%4,%5,%6,%7}, {%8,%9}, {%0,%1,%2,%3};"
        : "+f"(c[0]), "+f"(c[1]), "+f"(c[2]), "+f"(c[3])
        : "r"(a0), "r"(a1), "r"(a2), "r"(a3), "r"(b0), "r"(b1));
}
__device__ __forceinline__ float clampdt(float v) {
    return fminf(fmaxf(v, 1e-4f), 2.0f);
}
// k3 packing: pairs (k, k+4) adjacent for LDS.64 fragment loads
__device__ __forceinline__ int unpos(int c) {
    int slot = c & 7;
    return (c & ~7) + (slot >> 1) + ((slot & 1) << 2);
}
__device__ __forceinline__ int posf(int k) {
    return (k & ~7) + ((k & 3) << 1) + ((k & 4) >> 2);
}
// k1 packing (float4-A co-permutation): smem col -> memory k.
// mem k = 16*grp + 4*j + r maps to block (2*grp + (r>>1)), hw col (j, j+4 by r&1).
__device__ __forceinline__ int unpos2(int c) {
    return 16*(c >> 4) + 4*((c >> 1) & 3) + 2*((c >> 3) & 1) + (c & 1);
}

// ---------------------------------------------------------------------------
// Kernel 1: tf32 MMA projection + in-warp 16-token affine scan. Persistent
// grid 296. A-operands loaded as ONE float4 per lane per 16-k group (serves
// two k-blocks) via K co-permutation with the B smem packing (unpos2):
// A-gather wavefronts drop 4x vs scalar LDG.32.
// ---------------------------------------------------------------------------
__global__ __launch_bounds__(256, 2) void k1_mma(
    const float* __restrict__ xr_g, const float* __restrict__ xi_g,
    const float* __restrict__ logA, const float* __restrict__ Aph_g,
    const float* __restrict__ Bwr,  const float* __restrict__ Bwi,
    const float* __restrict__ dtw_g, const float* __restrict__ dtb_g)
{
    extern __shared__ float sm[];
    float* BRp = sm;                 // [72][136]
    float* BIp = BRp + 72*136;       // [72][136]
    float* nlA = BIp + 72*136;       // [512]
    float* aph = nlA + 512;          // [512]

    const int tid = threadIdx.x;
    for (int idx = tid; idx < 72*136; idx += 256) {
        int r = idx / 136, c = idx - r*136;
        float vr = 0.f, vi = 0.f;
        if (c < 128 && r < 66) {
            int k = unpos2(c);
            if (r < 64)      { vr = Bwr[r*128 + k];   vi = Bwi[r*128 + k]; }
            else if (r == 64){ vr = dtw_g[k];         vi = dtw_g[128 + k]; }
            else             { vr = dtw_g[256 + k];   vi = dtw_g[384 + k]; }
        }
        BRp[idx] = tf32f(vr);
        BIp[idx] = tf32f(vi);
    }
    for (int i = tid; i < 512; i += 256) {
        nlA[i] = -log1pf(expf(logA[i]));   // -softplus
        aph[i] = Aph_g[i];
    }
    __syncthreads();

    const int w = tid >> 5, l = tid & 31;
    const int q = l >> 2, j = l & 3;
    const float db0 = dtb_g[0], db1 = dtb_g[1];

    for (int grpi = blockIdx.x; grpi < 512; grpi += gridDim.x) {
        const int slice = grpi*8 + w;         // 0..4095
        const int bg = slice >> 7, s16 = slice & 127;
        const int b = bg >> 3, g = bg & 7;
        const int g6 = g*64;

        float cr[9][4], ci[8][4];
        #pragma unroll
        for (int t = 0; t < 9; ++t) { cr[t][0]=0.f; cr[t][1]=0.f; cr[t][2]=0.f; cr[t][3]=0.f; }
        #pragma unroll
        for (int t = 0; t < 8; ++t) { ci[t][0]=0.f; ci[t][1]=0.f; ci[t][2]=0.f; ci[t][3]=0.f; }

        const unsigned rowA = (unsigned)((b*2048 + s16*16 + q)*8 + g)*128u;
        const unsigned rowB = rowA + 8u*1024u;

        // ---- xr half: cr += xr*Bwr ; ci += xr*Bwi ; dt += xr*dtw_lo ----
        #pragma unroll 2
        for (int gk = 0; gk < 8; ++gk) {
            const unsigned mk = gk*16u + 4u*j;
            const float4 fA = *(const float4*)(xr_g + rowA + mk);
            const float4 fB = *(const float4*)(xr_g + rowB + mk);
            const uint32_t a0 = cvt_tf32(fA.x), a1 = cvt_tf32(fB.x);
            const uint32_t a2 = cvt_tf32(fA.y), a3 = cvt_tf32(fB.y);
            const uint32_t c0 = cvt_tf32(fA.z), c1 = cvt_tf32(fB.z);
            const uint32_t c2 = cvt_tf32(fA.w), c3 = cvt_tf32(fB.w);
            const int kc0 = gk*16 + 2*j;
            const int kc1 = kc0 + 8;
            #pragma unroll
            for (int nt = 0; nt < 9; ++nt) {
                const int rb = (nt*8 + q)*136;
                uint2 bb = *(const uint2*)&BRp[rb + kc0];
                mma8(cr[nt], a0, a1, a2, a3, bb.x, bb.y);
                bb = *(const uint2*)&BRp[rb + kc1];
                mma8(cr[nt], c0, c1, c2, c3, bb.x, bb.y);
            }
            #pragma unroll
            for (int nt = 0; nt < 8; ++nt) {
                const int rb = (nt*8 + q)*136;
                uint2 bb = *(const uint2*)&BIp[rb + kc0];
                mma8(ci[nt], a0, a1, a2, a3, bb.x, bb.y);
                bb = *(const uint2*)&BIp[rb + kc1];
                mma8(ci[nt], c0, c1, c2, c3, bb.x, bb.y);
            }
        }
        // ---- xi half: cr -= xi*Bwi ; ci += xi*Bwr ; dt += xi*dtw_hi ----
        #pragma unroll 2
        for (int gk = 0; gk < 8; ++gk) {
            const unsigned mk = gk*16u + 4u*j;
            const float4 fA = *(const float4*)(xi_g + rowA + mk);
            const float4 fB = *(const float4*)(xi_g + rowB + mk);
            const uint32_t a0 = cvt_tf32(fA.x), a1 = cvt_tf32(fB.x);
            const uint32_t a2 = cvt_tf32(fA.y), a3 = cvt_tf32(fB.y);
            const uint32_t c0 = cvt_tf32(fA.z), c1 = cvt_tf32(fB.z);
            const uint32_t c2 = cvt_tf32(fA.w), c3 = cvt_tf32(fB.w);
            const int kc0 = gk*16 + 2*j;
            const int kc1 = kc0 + 8;
            #pragma unroll
            for (int nt = 0; nt < 9; ++nt) {
                const int rb = (nt*8 + q)*136;
                const uint32_t m = (nt < 8) ? 0x80000000u : 0u;   // -Bwi, +dtw
                uint2 bb = *(const uint2*)&BIp[rb + kc0];
                mma8(cr[nt], a0, a1, a2, a3, bb.x ^ m, bb.y ^ m);
                bb = *(const uint2*)&BIp[rb + kc1];
                mma8(cr[nt], c0, c1, c2, c3, bb.x ^ m, bb.y ^ m);
            }
            #pragma unroll
            for (int nt = 0; nt < 8; ++nt) {
                const int rb = (nt*8 + q)*136;
                uint2 bb = *(const uint2*)&BRp[rb + kc0];
                mma8(ci[nt], a0, a1, a2, a3, bb.x, bb.y);
                bb = *(const uint2*)&BRp[rb + kc1];
                mma8(ci[nt], c0, c1, c2, c3, bb.x, bb.y);
            }
        }

        // ---- dt via shfl, clamp ----
        const int src = l & ~3;
        float dmL = __shfl_sync(0xffffffffu, cr[8][0], src);
        float dpL = __shfl_sync(0xffffffffu, cr[8][1], src);
        float dmH = __shfl_sync(0xffffffffu, cr[8][2], src);
        float dpH = __shfl_sync(0xffffffffu, cr[8][3], src);
        dmL = clampdt(__expf(dmL + db0));  dpL = clampdt(__expf(dpL + db1));
        dmH = clampdt(__expf(dmH + db0));  dpH = clampdt(__expf(dpH + db1));

        // ---- per-n: affine elements (MUFU), 16-token shfl scan, write ----
        const size_t idxL = ((size_t)bg*2048 + s16*16 + q)*64;
        const size_t idxH = idxL + (size_t)8*64;

        #pragma unroll
        for (int nt = 0; nt < 8; ++nt) {
            #pragma unroll
            for (int e = 0; e < 2; ++e) {
                const int n = nt*8 + 2*j + e;
                const float nl = nlA[g6 + n], ap = aph[g6 + n];
                float snL, csL, snH, csH;
                float amL = __expf(dmL*nl);
                __sincosf(dpL*ap, &snL, &csL);
                float aLr = amL*csL, aLi = amL*snL;
                float bLr = cr[nt][e]*dmL, bLi = ci[nt][e]*dmL;
                float amH = __expf(dmH*nl);
                __sincosf(dpH*ap, &snH, &csH);
                float aHr = amH*csH, aHi = amH*snH;
                float bHr = cr[nt][2+e]*dmH, bHi = ci[nt][2+e]*dmH;

                // Hillis-Steele over q (both halves simultaneously)
                #pragma unroll
                for (int st = 1; st <= 4; st <<= 1) {
                    const int dlt = 4*st;
                    float par = __shfl_up_sync(0xffffffffu, aLr, dlt);
                    float pai = __shfl_up_sync(0xffffffffu, aLi, dlt);
                    float pbr = __shfl_up_sync(0xffffffffu, bLr, dlt);
                    float pbi = __shfl_up_sync(0xffffffffu, bLi, dlt);
                    float qar = __shfl_up_sync(0xffffffffu, aHr, dlt);
                    float qai = __shfl_up_sync(0xffffffffu, aHi, dlt);
                    float qbr = __shfl_up_sync(0xffffffffu, bHr, dlt);
                    float qbi = __shfl_up_sync(0xffffffffu, bHi, dlt);
                    if (q >= st) {
                        float t1 = aLr*par - aLi*pai;
                        float t2 = aLr*pai + aLi*par;
                        float t3 = fmaf(aLr, pbr, fmaf(-aLi, pbi, bLr));
                        float t4 = fmaf(aLr, pbi, fmaf( aLi, pbr, bLi));
                        aLr = t1; aLi = t2; bLr = t3; bLi = t4;
                        t1 = aHr*qar - aHi*qai;
                        t2 = aHr*qai + aHi*qar;
                        t3 = fmaf(aHr, qbr, fmaf(-aHi, qbi, bHr));
                        t4 = fmaf(aHr, qbi, fmaf( aHi, qbr, bHi));
                        aHr = t1; aHi = t2; bHr = t3; bHi = t4;
                    }
                }
                // bridge: full prefix of tokens 0..7 lives at q==7 (lane 28+j)
                float f7ar = __shfl_sync(0xffffffffu, aLr, 28 + j);
                float f7ai = __shfl_sync(0xffffffffu, aLi, 28 + j);
                float f7br = __shfl_sync(0xffffffffu, bLr, 28 + j);
                float f7bi = __shfl_sync(0xffffffffu, bLi, 28 + j);
                float Har = aHr*f7ar - aHi*f7ai;
                float Hai = aHr*f7ai + aHi*f7ar;
                float Hbr = fmaf(aHr, f7br, fmaf(-aHi, f7bi, bHr));
                float Hbi = fmaf(aHr, f7bi, fmaf( aHi, f7br, bHi));

                g_hc[idxL + n] = make_float4(bLr, bLi, aLr, aLi);   // token q
                g_hc[idxH + n] = make_float4(Hbr, Hbi, Har, Hai);   // token q+8
            }
        }
    }
}

// ---------------------------------------------------------------------------
// Kernel 2b: sequential sub16 combine; renorm every 16th sub16 boundary.
// ---------------------------------------------------------------------------
__global__ __launch_bounds__(64) void k2b_combine(void)
{
    int bg = blockIdx.x;
    int n = threadIdx.x;
    float hr = 0.f, hi = 0.f;

    float4 ebuf[8];
    #pragma unroll
    for (int jj = 0; jj < 8; ++jj)
        ebuf[jj] = g_hc[((size_t)bg*SS + jj*SUB + 15)*NN + n];

    for (int s0 = 0; s0 < NSUB; s0 += 8) {
        #pragma unroll
        for (int jj = 0; jj < 8; ++jj) {
            float4 e = ebuf[jj];
            int nsub = s0 + 8 + jj;
            if (nsub < NSUB)
                ebuf[jj] = g_hc[((size_t)bg*SS + nsub*SUB + 15)*NN + n];
            int sub = s0 + jj;
            g_hin[(bg*NSUB + sub)*NN + n] = make_float2(hr, hi);
            float nr = fmaf(e.z, hr, fmaf(-e.w, hi, e.x));
            float ni = fmaf(e.z, hi, fmaf( e.w, hr, e.y));
            if ((sub & 15) == 15) {
                float nm = sqrtf(nr*nr + ni*ni + 1e-8f);
                float sc = fminf(nm, 100.0f)/nm;
                nr *= sc; ni *= sc;
            }
            hr = nr; hi = ni;
        }
    }
}

// ---------------------------------------------------------------------------
// Kernel 3: correction + tf32 MMA C-projection. Persistent (grid 296),
// CTA tile = 64 tokens, block 512, 2 CTAs/SM; P/Q fill amortized.
// ---------------------------------------------------------------------------
__global__ __launch_bounds__(512, 2) void k3_mma(
    const float* __restrict__ Cwr, const float* __restrict__ Cwi,
    float* __restrict__ out)
{
    extern __shared__ float sm[];
    float* P  = sm;             // [128 d][72]  Cwr, k-pair packed
    float* Q  = P + 128*72;     // [128 d][72]  Cwi
    float* hs = Q + 128*72;     // [64 tok][136]  [hr | hi], k-pair packed

    const int tid = threadIdx.x;
    for (int idx = tid; idx < 128*72; idx += 512) {
        int d = idx / 72, c = idx - d*72;
        float vp = 0.f, vq = 0.f;
        if (c < 64) {
            int k = unpos(c);
            vp = Cwr[d*64 + k];
            vq = Cwi[d*64 + k];
        }
        P[idx] = tf32f(vp);
        Q[idx] = tf32f(vq);
    }

    const int w = tid >> 5, l = tid & 31;
    const int q = l >> 2, j = l & 3;
    const int mrow  = w & 3;           // which 16-token block
    const int nhalf = (w >> 2) & 1;    // which 8 nt-tiles
    const int half  = w >> 3;          // 0 = yR, 1 = yI
    const int row0 = mrow*16 + q;
    const int ntb = nhalf*8;

    const float* Blo = half ? Q : P;     // k < 64
    const float* Bhi = half ? P : Q;     // k >= 64
    const uint32_t mhi = half ? 0u : 0x80000000u;   // negate Q for yR
    float* outh = out + (size_t)half * ((size_t)NTOK*128);

    for (int tile = blockIdx.x; tile < NTOK/64; tile += gridDim.x) {
        const int tau_base = tile*64;

        // ---- correction prologue: 64 tok x 64 n ----
        #pragma unroll
        for (int ii = 0; ii < 8; ++ii) {
            int cell = ii*512 + tid;
            int tl = cell >> 6, n = cell & 63;
            int tau = tau_base + tl;
            int b = tau >> 14, g = tau & 7, s = (tau >> 3) & 2047;
            int bg = b*8 + g;
            float4 hc = g_hc[((size_t)bg*2048 + s)*64 + n];
            float2 hin = g_hin[(bg*NSUB + (s >> 4))*64 + n];
            float hr = fmaf(hc.z, hin.x, fmaf(-hc.w, hin.y, hc.x));
            float hi = fmaf(hc.z, hin.y, fmaf( hc.w, hin.x, hc.y));
            if ((s & 255) == 255) {
                float nm = sqrtf(hr*hr + hi*hi + 1e-8f);
                float sc = fminf(nm, 100.0f)/nm;
                hr *= sc; hi *= sc;
            }
            int pos = posf(n);
            hs[tl*136 + pos]      = tf32f(hr);
            hs[tl*136 + 64 + pos] = tf32f(hi);
        }
        __syncthreads();

        float y[8][4];
        #pragma unroll
        for (int t = 0; t < 8; ++t) { y[t][0]=0.f; y[t][1]=0.f; y[t][2]=0.f; y[t][3]=0.f; }

        // ---- hr half (k < 64) ----
        #pragma unroll
        for (int ks = 0; ks < 8; ++ks) {
            const int kc = ks*8 + 2*j;
            uint2 aa0 = *(const uint2*)&hs[row0*136 + kc];
            uint2 aa1 = *(const uint2*)&hs[(row0 + 8)*136 + kc];
            #pragma unroll
            for (int t = 0; t < 8; ++t) {
                uint2 bb = *(const uint2*)&Blo[((ntb + t)*8 + q)*72 + kc];
                mma8(y[t], aa0.x, aa1.x, aa0.y, aa1.y, bb.x, bb.y);
            }
        }
        // ---- hi half (k >= 64) ----
        #pragma unroll
        for (int ks = 0; ks < 8; ++ks) {
            const int kc = ks*8 + 2*j;
            uint2 aa0 = *(const uint2*)&hs[row0*136 + 64 + kc];
            uint2 aa1 = *(const uint2*)&hs[(row0 + 8)*136 + 64 + kc];
            #pragma unroll
            for (int t = 0; t < 8; ++t) {
                uint2 bb = *(const uint2*)&Bhi[((ntb + t)*8 + q)*72 + kc];
                mma8(y[t], aa0.x, aa1.x, aa0.y, aa1.y, bb.x ^ mhi, bb.y ^ mhi);
            }
        }

        // ---- output ----
        #pragma unroll
        for (int t = 0; t < 8; ++t) {
            int d0 = (ntb + t)*8 + 2*j;
            size_t tA = (size_t)(tau_base + row0)*128 + d0;
            size_t tB = (size_t)(tau_base + row0 + 8)*128 + d0;
            *(float2*)&outh[tA] = make_float2(y[t][0], y[t][1]);
            *(float2*)&outh[tB] = make_float2(y[t][2], y[t][3]);
        }
        __syncthreads();   // protect hs before next tile's prologue
    }
}

// ---------------------------------------------------------------------------
extern "C" void kernel_launch(void* const* d_in, const int* in_sizes, int n_in,
                              void* d_out, int out_size)
{
    const float* x_r  = (const float*)d_in[0];
    const float* x_i  = (const float*)d_in[1];
    const float* logA = (const float*)d_in[2];
    const float* Aph  = (const float*)d_in[3];
    const float* Bwr  = (const float*)d_in[4];
    const float* Bwi  = (const float*)d_in[5];
    const float* Cwr  = (const float*)d_in[6];
    const float* Cwi  = (const float*)d_in[7];
    const float* dtw  = (const float*)d_in[8];
    const float* dtb  = (const float*)d_in[9];
    float* out = (float*)d_out;

    const int smem1 = (72*136*2 + 1024) * 4;          // 82,432 B
    const int smem3 = (128*72*2 + 64*136) * 4;        // 108,544 B
    cudaFuncSetAttribute(k1_mma, cudaFuncAttributeMaxDynamicSharedMemorySize, smem1);
    cudaFuncSetAttribute(k3_mma, cudaFuncAttributeMaxDynamicSharedMemorySize, smem3);

    k1_mma<<<296, 256, smem1>>>(x_r, x_i, logA, Aph, Bwr, Bwi, dtw, dtb);
    k2b_combine<<<BG, 64>>>();
    k3_mma<<<296, 512, smem3>>>(Cwr, Cwi, out);
}

// round 17
// speedup vs baseline: 1.3558x; 1.0179x over previous
#include <cuda_runtime.h>
#include <math.h>
#include <stdint.h>

// Fixed problem shapes
#define BB   4
#define SS   2048
#define GG   8
#define DD   128
#define NN   64
#define BG   (BB*GG)          // 32
#define NTOK (BB*SS*GG)       // 65536
#define SUB  16
#define NSUB (SS/SUB)         // 128

// Scratch (device globals; no allocation allowed)
__device__ float4 g_hc[BG*SS*NN];      // (hl_r, hl_i, c_r, c_i)  64 MB
__device__ float2 g_hin[BG*NSUB*NN];   // sub16 input states       2 MB

// ---------------- helpers ----------------
__device__ __forceinline__ uint32_t cvt_tf32(float f) {
    uint32_t u; asm("cvt.rna.tf32.f32 %0, %1;" : "=r"(u) : "f"(f)); return u;
}
__device__ __forceinline__ float tf32f(float f) {
    return __uint_as_float(cvt_tf32(f));
}
__device__ __forceinline__ void mma8(float* c, uint32_t a0, uint32_t a1,
                                     uint32_t a2, uint32_t a3,
                                     uint32_t b0, uint32_t b1) {
    asm("mma.sync.aligned.m16n8k8.row.col.f32.tf32.tf32.f32 "
        "{%0,%1,%2,%3}, {%4,%5,%6,%7}, {%8,%9}, {%0,%1,%2,%3};"
        : "+f"(c[0]), "+f"(c[1]), "+f"(c[2]), "+f"(c[3])
        : "r"(a0), "r"(a1), "r"(a2), "r"(a3), "r"(b0), "r"(b1));
}
__device__ __forceinline__ float clampdt(float v) {
    return fminf(fmaxf(v, 1e-4f), 2.0f);
}
// k3 packing: pairs (k, k+4) adjacent for LDS.64 fragment loads
__device__ __forceinline__ int unpos(int c) {
    int slot = c & 7;
    return (c & ~7) + (slot >> 1) + ((slot & 1) << 2);
}
__device__ __forceinline__ int posf(int k) {
    return (k & ~7) + ((k & 3) << 1) + ((k & 4) >> 2);
}
// k1 packing (float4-A co-permutation): smem col -> memory k.
__device__ __forceinline__ int unpos2(int c) {
    return 16*(c >> 4) + 4*((c >> 1) & 3) + 2*((c >> 3) & 1) + (c & 1);
}

// ---------------------------------------------------------------------------
// Kernel 1: tf32 MMA projection + in-warp 16-token affine scan. Persistent
// grid 296. A-operands loaded as ONE float4 per lane per 16-k group via K
// co-permutation (unpos2). Token-row remap: row q <-> token 2q, row q+8 <->
// token 2q+1 -> each lane owns an ADJACENT token pair; scan = serial pair
// compose + 8-segment Hillis-Steele (16 shfl per n instead of 36).
// ---------------------------------------------------------------------------
__global__ __launch_bounds__(256, 2) void k1_mma(
    const float* __restrict__ xr_g, const float* __restrict__ xi_g,
    const float* __restrict__ logA, const float* __restrict__ Aph_g,
    const float* __restrict__ Bwr,  const float* __restrict__ Bwi,
    const float* __restrict__ dtw_g, const float* __restrict__ dtb_g)
{
    extern __shared__ float sm[];
    float* BRp = sm;                 // [72][136]
    float* BIp = BRp + 72*136;       // [72][136]
    float* nlA = BIp + 72*136;       // [512]
    float* aph = nlA + 512;          // [512]

    const int tid = threadIdx.x;
    for (int idx = tid; idx < 72*136; idx += 256) {
        int r = idx / 136, c = idx - r*136;
        float vr = 0.f, vi = 0.f;
        if (c < 128 && r < 66) {
            int k = unpos2(c);
            if (r < 64)      { vr = Bwr[r*128 + k];   vi = Bwi[r*128 + k]; }
            else if (r == 64){ vr = dtw_g[k];         vi = dtw_g[128 + k]; }
            else             { vr = dtw_g[256 + k];   vi = dtw_g[384 + k]; }
        }
        BRp[idx] = tf32f(vr);
        BIp[idx] = tf32f(vi);
    }
    for (int i = tid; i < 512; i += 256) {
        nlA[i] = -log1pf(expf(logA[i]));   // -softplus
        aph[i] = Aph_g[i];
    }
    __syncthreads();

    const int w = tid >> 5, l = tid & 31;
    const int q = l >> 2, j = l & 3;
    const float db0 = dtb_g[0], db1 = dtb_g[1];

    for (int grpi = blockIdx.x; grpi < 512; grpi += gridDim.x) {
        const int slice = grpi*8 + w;         // 0..4095
        const int bg = slice >> 7, s16 = slice & 127;
        const int b = bg >> 3, g = bg & 7;
        const int g6 = g*64;

        float cr[9][4], ci[8][4];
        #pragma unroll
        for (int t = 0; t < 9; ++t) { cr[t][0]=0.f; cr[t][1]=0.f; cr[t][2]=0.f; cr[t][3]=0.f; }
        #pragma unroll
        for (int t = 0; t < 8; ++t) { ci[t][0]=0.f; ci[t][1]=0.f; ci[t][2]=0.f; ci[t][3]=0.f; }

        // row q -> token 2q ; row q+8 -> token 2q+1 (adjacent)
        const unsigned rowA = (unsigned)((b*2048 + s16*16 + 2*q)*8 + g)*128u;
        const unsigned rowB = rowA + 1024u;

        // ---- xr half: cr += xr*Bwr ; ci += xr*Bwi ; dt += xr*dtw_lo ----
        #pragma unroll 2
        for (int gk = 0; gk < 8; ++gk) {
            const unsigned mk = gk*16u + 4u*j;
            const float4 fA = *(const float4*)(xr_g + rowA + mk);
            const float4 fB = *(const float4*)(xr_g + rowB + mk);
            const uint32_t a0 = cvt_tf32(fA.x), a1 = cvt_tf32(fB.x);
            const uint32_t a2 = cvt_tf32(fA.y), a3 = cvt_tf32(fB.y);
            const uint32_t c0 = cvt_tf32(fA.z), c1 = cvt_tf32(fB.z);
            const uint32_t c2 = cvt_tf32(fA.w), c3 = cvt_tf32(fB.w);
            const int kc0 = gk*16 + 2*j;
            const int kc1 = kc0 + 8;
            #pragma unroll
            for (int nt = 0; nt < 9; ++nt) {
                const int rb = (nt*8 + q)*136;
                uint2 bb = *(const uint2*)&BRp[rb + kc0];
                mma8(cr[nt], a0, a1, a2, a3, bb.x, bb.y);
                bb = *(const uint2*)&BRp[rb + kc1];
                mma8(cr[nt], c0, c1, c2, c3, bb.x, bb.y);
            }
            #pragma unroll
            for (int nt = 0; nt < 8; ++nt) {
                const int rb = (nt*8 + q)*136;
                uint2 bb = *(const uint2*)&BIp[rb + kc0];
                mma8(ci[nt], a0, a1, a2, a3, bb.x, bb.y);
                bb = *(const uint2*)&BIp[rb + kc1];
                mma8(ci[nt], c0, c1, c2, c3, bb.x, bb.y);
            }
        }
        // ---- xi half: cr -= xi*Bwi ; ci += xi*Bwr ; dt += xi*dtw_hi ----
        #pragma unroll 2
        for (int gk = 0; gk < 8; ++gk) {
            const unsigned mk = gk*16u + 4u*j;
            const float4 fA = *(const float4*)(xi_g + rowA + mk);
            const float4 fB = *(const float4*)(xi_g + rowB + mk);
            const uint32_t a0 = cvt_tf32(fA.x), a1 = cvt_tf32(fB.x);
            const uint32_t a2 = cvt_tf32(fA.y), a3 = cvt_tf32(fB.y);
            const uint32_t c0 = cvt_tf32(fA.z), c1 = cvt_tf32(fB.z);
            const uint32_t c2 = cvt_tf32(fA.w), c3 = cvt_tf32(fB.w);
            const int kc0 = gk*16 + 2*j;
            const int kc1 = kc0 + 8;
            #pragma unroll
            for (int nt = 0; nt < 9; ++nt) {
                const int rb = (nt*8 + q)*136;
                const uint32_t m = (nt < 8) ? 0x80000000u : 0u;   // -Bwi, +dtw
                uint2 bb = *(const uint2*)&BIp[rb + kc0];
                mma8(cr[nt], a0, a1, a2, a3, bb.x ^ m, bb.y ^ m);
                bb = *(const uint2*)&BIp[rb + kc1];
                mma8(cr[nt], c0, c1, c2, c3, bb.x ^ m, bb.y ^ m);
            }
            #pragma unroll
            for (int nt = 0; nt < 8; ++nt) {
                const int rb = (nt*8 + q)*136;
                uint2 bb = *(const uint2*)&BRp[rb + kc0];
                mma8(ci[nt], a0, a1, a2, a3, bb.x, bb.y);
                bb = *(const uint2*)&BRp[rb + kc1];
                mma8(ci[nt], c0, c1, c2, c3, bb.x, bb.y);
            }
        }

        // ---- dt via shfl, clamp (cols 0,1 = token 2q; cols 2,3 = token 2q+1)
        const int src = l & ~3;
        float dmA = __shfl_sync(0xffffffffu, cr[8][0], src);
        float dpA = __shfl_sync(0xffffffffu, cr[8][1], src);
        float dmB = __shfl_sync(0xffffffffu, cr[8][2], src);
        float dpB = __shfl_sync(0xffffffffu, cr[8][3], src);
        dmA = clampdt(__expf(dmA + db0));  dpA = clampdt(__expf(dpA + db1));
        dmB = clampdt(__expf(dmB + db0));  dpB = clampdt(__expf(dpB + db1));

        // ---- per-n: pair compose + 8-segment scan (16 shfl per n) ----
        const size_t idx0 = ((size_t)bg*2048 + s16*16 + 2*q)*64;   // token 2q
        const size_t idx1 = idx0 + 64;                             // token 2q+1

        #pragma unroll
        for (int nt = 0; nt < 8; ++nt) {
            #pragma unroll
            for (int e = 0; e < 2; ++e) {
                const int n = nt*8 + 2*j + e;
                const float nl = nlA[g6 + n], ap = aph[g6 + n];
                float snA, csA, snB, csB;
                float amA = __expf(dmA*nl);
                __sincosf(dpA*ap, &snA, &csA);
                const float aAr = amA*csA, aAi = amA*snA;
                const float bAr = cr[nt][e]*dmA, bAi = ci[nt][e]*dmA;
                float amB = __expf(dmB*nl);
                __sincosf(dpB*ap, &snB, &csB);
                const float aBr = amB*csB, aBi = amB*snB;
                const float bBr = cr[nt][2+e]*dmB, bBi = ci[nt][2+e]*dmB;

                // segment = eB ∘ eA
                float sar = aBr*aAr - aBi*aAi;
                float sai = aBr*aAi + aBi*aAr;
                float sbr = fmaf(aBr, bAr, fmaf(-aBi, bAi, bBr));
                float sbi = fmaf(aBr, bAi, fmaf( aBi, bAr, bBi));

                // inclusive Hillis-Steele over 8 q-segments
                #pragma unroll
                for (int st = 1; st <= 4; st <<= 1) {
                    const int dlt = 4*st;
                    float par = __shfl_up_sync(0xffffffffu, sar, dlt);
                    float pai = __shfl_up_sync(0xffffffffu, sai, dlt);
                    float pbr = __shfl_up_sync(0xffffffffu, sbr, dlt);
                    float pbi = __shfl_up_sync(0xffffffffu, sbi, dlt);
                    if (q >= st) {
                        float t1 = sar*par - sai*pai;
                        float t2 = sar*pai + sai*par;
                        float t3 = fmaf(sar, pbr, fmaf(-sai, pbi, sbr));
                        float t4 = fmaf(sar, pbi, fmaf( sai, pbr, sbi));
                        sar = t1; sai = t2; sbr = t3; sbi = t4;
                    }
                }
                // exclusive prefix (segment q-1), identity for q==0
                float xar = __shfl_up_sync(0xffffffffu, sar, 4);
                float xai = __shfl_up_sync(0xffffffffu, sai, 4);
                float xbr = __shfl_up_sync(0xffffffffu, sbr, 4);
                float xbi = __shfl_up_sync(0xffffffffu, sbi, 4);
                if (q == 0) { xar = 1.f; xai = 0.f; xbr = 0.f; xbi = 0.f; }

                // token 2q: e_A ∘ X
                float h0r = fmaf(aAr, xbr, fmaf(-aAi, xbi, bAr));
                float h0i = fmaf(aAr, xbi, fmaf( aAi, xbr, bAi));
                float c0r = aAr*xar - aAi*xai;
                float c0i = aAr*xai + aAi*xar;
                // token 2q+1: inclusive S
                g_hc[idx0 + n] = make_float4(h0r, h0i, c0r, c0i);
                g_hc[idx1 + n] = make_float4(sbr, sbi, sar, sai);
            }
        }
    }
}

// ---------------------------------------------------------------------------
// Kernel 2b: sequential sub16 combine; renorm every 16th sub16 boundary.
// ---------------------------------------------------------------------------
__global__ __launch_bounds__(64) void k2b_combine(void)
{
    int bg = blockIdx.x;
    int n = threadIdx.x;
    float hr = 0.f, hi = 0.f;

    float4 ebuf[8];
    #pragma unroll
    for (int jj = 0; jj < 8; ++jj)
        ebuf[jj] = g_hc[((size_t)bg*SS + jj*SUB + 15)*NN + n];

    for (int s0 = 0; s0 < NSUB; s0 += 8) {
        #pragma unroll
        for (int jj = 0; jj < 8; ++jj) {
            float4 e = ebuf[jj];
            int nsub = s0 + 8 + jj;
            if (nsub < NSUB)
                ebuf[jj] = g_hc[((size_t)bg*SS + nsub*SUB + 15)*NN + n];
            int sub = s0 + jj;
            g_hin[(bg*NSUB + sub)*NN + n] = make_float2(hr, hi);
            float nr = fmaf(e.z, hr, fmaf(-e.w, hi, e.x));
            float ni = fmaf(e.z, hi, fmaf( e.w, hr, e.y));
            if ((sub & 15) == 15) {
                float nm = sqrtf(nr*nr + ni*ni + 1e-8f);
                float sc = fminf(nm, 100.0f)/nm;
                nr *= sc; ni *= sc;
            }
            hr = nr; hi = ni;
        }
    }
}

// ---------------------------------------------------------------------------
// Kernel 3: correction + tf32 MMA C-projection. Persistent (grid 296),
// CTA tile = 64 tokens, block 512, 2 CTAs/SM; P/Q fill amortized.
// ---------------------------------------------------------------------------
__global__ __launch_bounds__(512, 2) void k3_mma(
    const float* __restrict__ Cwr, const float* __restrict__ Cwi,
    float* __restrict__ out)
{
    extern __shared__ float sm[];
    float* P  = sm;             // [128 d][72]  Cwr, k-pair packed
    float* Q  = P + 128*72;     // [128 d][72]  Cwi
    float* hs = Q + 128*72;     // [64 tok][136]  [hr | hi], k-pair packed

    const int tid = threadIdx.x;
    for (int idx = tid; idx < 128*72; idx += 512) {
        int d = idx / 72, c = idx - d*72;
        float vp = 0.f, vq = 0.f;
        if (c < 64) {
            int k = unpos(c);
            vp = Cwr[d*64 + k];
            vq = Cwi[d*64 + k];
        }
        P[idx] = tf32f(vp);
        Q[idx] = tf32f(vq);
    }

    const int w = tid >> 5, l = tid & 31;
    const int q = l >> 2, j = l & 3;
    const int mrow  = w & 3;           // which 16-token block
    const int nhalf = (w >> 2) & 1;    // which 8 nt-tiles
    const int half  = w >> 3;          // 0 = yR, 1 = yI
    const int row0 = mrow*16 + q;
    const int ntb = nhalf*8;

    const float* Blo = half ? Q : P;     // k < 64
    const float* Bhi = half ? P : Q;     // k >= 64
    const uint32_t mhi = half ? 0u : 0x80000000u;   // negate Q for yR
    float* outh = out + (size_t)half * ((size_t)NTOK*128);

    for (int tile = blockIdx.x; tile < NTOK/64; tile += gridDim.x) {
        const int tau_base = tile*64;

        // ---- correction prologue: 64 tok x 64 n ----
        #pragma unroll
        for (int ii = 0; ii < 8; ++ii) {
            int cell = ii*512 + tid;
            int tl = cell >> 6, n = cell & 63;
            int tau = tau_base + tl;
            int b = tau >> 14, g = tau & 7, s = (tau >> 3) & 2047;
            int bg = b*8 + g;
            float4 hc = g_hc[((size_t)bg*2048 + s)*64 + n];
            float2 hin = g_hin[(bg*NSUB + (s >> 4))*64 + n];
            float hr = fmaf(hc.z, hin.x, fmaf(-hc.w, hin.y, hc.x));
            float hi = fmaf(hc.z, hin.y, fmaf( hc.w, hin.x, hc.y));
            if ((s & 255) == 255) {
                float nm = sqrtf(hr*hr + hi*hi + 1e-8f);
                float sc = fminf(nm, 100.0f)/nm;
                hr *= sc; hi *= sc;
            }
            int pos = posf(n);
            hs[tl*136 + pos]      = tf32f(hr);
            hs[tl*136 + 64 + pos] = tf32f(hi);
        }
        __syncthreads();

        float y[8][4];
        #pragma unroll
        for (int t = 0; t < 8; ++t) { y[t][0]=0.f; y[t][1]=0.f; y[t][2]=0.f; y[t][3]=0.f; }

        // ---- hr half (k < 64) ----
        #pragma unroll
        for (int ks = 0; ks < 8; ++ks) {
            const int kc = ks*8 + 2*j;
            uint2 aa0 = *(const uint2*)&hs[row0*136 + kc];
            uint2 aa1 = *(const uint2*)&hs[(row0 + 8)*136 + kc];
            #pragma unroll
            for (int t = 0; t < 8; ++t) {
                uint2 bb = *(const uint2*)&Blo[((ntb + t)*8 + q)*72 + kc];
                mma8(y[t], aa0.x, aa1.x, aa0.y, aa1.y, bb.x, bb.y);
            }
        }
        // ---- hi half (k >= 64) ----
        #pragma unroll
        for (int ks = 0; ks < 8; ++ks) {
            const int kc = ks*8 + 2*j;
            uint2 aa0 = *(const uint2*)&hs[row0*136 + 64 + kc];
            uint2 aa1 = *(const uint2*)&hs[(row0 + 8)*136 + 64 + kc];
            #pragma unroll
            for (int t = 0; t < 8; ++t) {
                uint2 bb = *(const uint2*)&Bhi[((ntb + t)*8 + q)*72 + kc];
                mma8(y[t], aa0.x, aa1.x, aa0.y, aa1.y, bb.x ^ mhi, bb.y ^ mhi);
            }
        }

        // ---- output ----
        #pragma unroll
        for (int t = 0; t < 8; ++t) {
            int d0 = (ntb + t)*8 + 2*j;
            size_t tA = (size_t)(tau_base + row0)*128 + d0;
            size_t tB = (size_t)(tau_base + row0 + 8)*128 + d0;
            *(float2*)&outh[tA] = make_float2(y[t][0], y[t][1]);
            *(float2*)&outh[tB] = make_float2(y[t][2], y[t][3]);
        }
        __syncthreads();   // protect hs before next tile's prologue
    }
}

// ---------------------------------------------------------------------------
extern "C" void kernel_launch(void* const* d_in, const int* in_sizes, int n_in,
                              void* d_out, int out_size)
{
    const float* x_r  = (const float*)d_in[0];
    const float* x_i  = (const float*)d_in[1];
    const float* logA = (const float*)d_in[2];
    const float* Aph  = (const float*)d_in[3];
    const float* Bwr  = (const float*)d_in[4];
    const float* Bwi  = (const float*)d_in[5];
    const float* Cwr  = (const float*)d_in[6];
    const float* Cwi  = (const float*)d_in[7];
    const float* dtw  = (const float*)d_in[8];
    const float* dtb  = (const float*)d_in[9];
    float* out = (float*)d_out;

    const int smem1 = (72*136*2 + 1024) * 4;          // 82,432 B
    const int smem3 = (128*72*2 + 64*136) * 4;        // 108,544 B
    cudaFuncSetAttribute(k1_mma, cudaFuncAttributeMaxDynamicSharedMemorySize, smem1);
    cudaFuncSetAttribute(k3_mma, cudaFuncAttributeMaxDynamicSharedMemorySize, smem3);

    k1_mma<<<296, 256, smem1>>>(x_r, x_i, logA, Aph, Bwr, Bwi, dtw, dtb);
    k2b_combine<<<BG, 64>>>();
    k3_mma<<<296, 512, smem3>>>(Cwr, Cwi, out);
}